// round 12
// baseline (speedup 1.0000x reference)
#include <cuda_runtime.h>
#include <math.h>
#include <stdint.h>

// ---------------- constants ----------------
#define N_PIX (480*640)
#define NM    (480*480)          // one 480x480 plane
#define N1    (8*20*480*480)     // one full (bs,20,480,480) tensor
#define ZALL  48
#define ZLO   13                 // ah range [13,35)
#define ZHI   35
#define ZSEM  22                 // ZHI-ZLO
#define NCELL (8*100*100)

// ---------------- device scratch ----------------
__device__ float g_vox0[NCELL*ZALL];            // [b][x][y][z]        15MB (ch0 counts)
__device__ float g_sem [NCELL*ZSEM*16];         // [b][x][y][zr][ch]  113MB (sem feats)
__device__ float g_proj[8*19*100*100];          // [b][plane][y][x]; 0=map 1=exp 2..17=sem 18=stair
__device__ float g_par[32];                     // per b: cos, sin, stx, sty
__device__ int   g_sxy[2];                      // stair circle center (x, y), batch 0

// ---------------- vector reduction helper ----------------
__device__ __forceinline__ void red4(float* p, float a, float b, float c, float d) {
    asm volatile("red.global.add.v4.f32 [%0], {%1,%2,%3,%4};"
                 :: "l"(p), "f"(a), "f"(b), "f"(c), "f"(d) : "memory");
}

// ---------------- K0: poses + transform params ----------------
__global__ void k_pose(const float* __restrict__ pose_obs,
                       const float* __restrict__ poses_last,
                       float* __restrict__ out_pose) {
    int b = threadIdx.x;
    if (b >= 8) return;
    const float DEGf = 57.29577951308232f;
    float tr = poses_last[b*3+2] / DEGf;
    float s = sinf(tr), c = cosf(tr);
    float ny = poses_last[b*3+1] + pose_obs[b*3+0]*s + pose_obs[b*3+1]*c;
    float nx = poses_last[b*3+0] + pose_obs[b*3+0]*c - pose_obs[b*3+1]*s;
    float no = poses_last[b*3+2] + pose_obs[b*3+2]*DEGf;
    no = fmodf(no - 180.0f, 360.0f) + 180.0f;
    no = fmodf(no + 180.0f, 360.0f) - 180.0f;
    out_pose[b*3+0] = nx; out_pose[b*3+1] = ny; out_pose[b*3+2] = no;

    float stx = -(nx*100.0f/5.0f - 240.0f)/240.0f;
    float sty = -(ny*100.0f/5.0f - 240.0f)/240.0f;
    float st_t = (90.0f - no) * 0.017453292519943295f;
    g_par[b*4+0] = cosf(st_t);
    g_par[b*4+1] = sinf(st_t);
    g_par[b*4+2] = stx;
    g_par[b*4+3] = sty;
    if (b == 0) {
        int sy = (int)(ny*100.0f/5.0f); sy = min(max(sy,30),449);
        int sx = (int)(nx*100.0f/5.0f); sx = min(max(sx,30),449);
        g_sxy[0] = sx; g_sxy[1] = sy;
    }
}

// ---------------- K1: trilinear splat ----------------
__global__ void k_splat(const float* __restrict__ obs,
                        const float* __restrict__ eve, float camf) {
    int t = blockIdx.x*blockDim.x + threadIdx.x;
    if (t >= 8*240*320) return;
    int j = t % 320;
    int i = (t/320) % 240;
    int b = t / (320*240);
    const float* ob = obs + (size_t)b*20*N_PIX;

    float d = ob[(size_t)3*N_PIX + (size_t)(2*i)*640 + 2*j];
    float X = ((float)(2*j) - 319.5f) * d / camf;
    float Z = ((float)(479 - 2*i) - 239.5f) * d / camf;
    float th = eve[b] * 0.017453292519943295f;
    float ct = cosf(th), st = sinf(th);
    float Yr = ct*d - st*Z;
    float Zr = st*d + ct*Z + 88.0f;
    float Xs = X + 250.0f;
    float cx = (Xs/5.0f - 50.0f)/100.0f*2.0f;
    float cy = (Yr/5.0f - 50.0f)/100.0f*2.0f;
    float cz = (Zr/5.0f - 16.0f)/48.0f*2.0f;
    float pos[3] = { cx*50.0f+50.0f, cy*50.0f+50.0f, cz*24.0f+24.0f };
    const int gd[3] = {100,100,48};

    int   ip[3][2];
    float w [3][2];
    #pragma unroll
    for (int dd=0; dd<3; dd++) {
        float fl = floorf(pos[dd]);
        #pragma unroll
        for (int ix=0; ix<2; ix++) {
            float pix = fl + (float)ix;
            bool safe = (pix > 0.0f) && (pix < (float)gd[dd]);
            w[dd][ix]  = safe ? (1.0f - fabsf(pos[dd]-pix)) : 0.0f;
            ip[dd][ix] = safe ? (int)pix : 0;
        }
    }

    float fs[16];
    #pragma unroll
    for (int c=0;c<16;c++) {
        const float2* p0 = (const float2*)(ob + (size_t)(4+c)*N_PIX + (size_t)(2*i)*640 + 2*j);
        const float2* p1 = (const float2*)((const float*)p0 + 640);
        float2 a = *p0, bb = *p1;
        fs[c] = (a.x + a.y + bb.x + bb.y) * 0.25f;
    }

    #pragma unroll
    for (int a=0;a<2;a++)
    #pragma unroll
    for (int e=0;e<2;e++) {
        float w01 = w[0][a]*w[1][e];
        if (w01 == 0.0f) continue;
        size_t cell = ((size_t)b*100 + ip[0][a])*100 + ip[1][e];
        #pragma unroll
        for (int f=0;f<2;f++) {
            float ww = w01*w[2][f];
            if (ww == 0.0f) continue;
            int z = ip[2][f];
            atomicAdd(&g_vox0[cell*ZALL + z], ww);
            if (z >= ZLO && z < ZHI) {
                float* p = g_sem + (cell*ZSEM + (z-ZLO))*16;
                red4(p,    fs[0]*ww,  fs[1]*ww,  fs[2]*ww,  fs[3]*ww);
                red4(p+4,  fs[4]*ww,  fs[5]*ww,  fs[6]*ww,  fs[7]*ww);
                red4(p+8,  fs[8]*ww,  fs[9]*ww,  fs[10]*ww, fs[11]*ww);
                red4(p+12, fs[12]*ww, fs[13]*ww, fs[14]*ww, fs[15]*ww);
            }
        }
    }
}

// ---------------- K2: all projections (fused) + re-zero ----------------
// group-major indexing: g = idx / NCELL, cell = idx % NCELL.
// g 0..3: sem channel groups (4 ch each). g 4: vox0 (map/exp/stair planes).
__global__ void __launch_bounds__(256) k_proj() {
    int idx = blockIdx.x*blockDim.x + threadIdx.x;
    if (idx >= 5*NCELL) return;
    int g    = idx / NCELL;
    int cell = idx - g*NCELL;      // b*10000 + x*100 + y
    int y = cell % 100;
    int x = (cell/100) % 100;
    int b = cell / 10000;

    if (g < 4) {
        float4* v = (float4*)(g_sem + (size_t)cell*ZSEM*16) + g;   // stride 4 float4 per z
        float a0=0.f, a1=0.f, a2=0.f, a3=0.f;
        const float4 z4 = make_float4(0.f,0.f,0.f,0.f);
        #pragma unroll
        for (int half=0; half<2; half++) {
            float4 r[11];
            #pragma unroll
            for (int z=0; z<11; z++) r[z] = v[(half*11 + z)*4];
            #pragma unroll
            for (int z=0; z<11; z++) v[(half*11 + z)*4] = z4;
            #pragma unroll
            for (int z=0; z<11; z++) {
                a0 += rintf(r[z].x);
                a1 += rintf(r[z].y);
                a2 += rintf(r[z].z);
                a3 += rintf(r[z].w);
            }
        }
        size_t po = (size_t)b*19*10000 + (size_t)(2 + g*4)*10000 + (size_t)y*100 + x;
        g_proj[po]         = fminf(fmaxf(a0*0.2f, 0.f), 1.f);
        g_proj[po+10000]   = fminf(fmaxf(a1*0.2f, 0.f), 1.f);
        g_proj[po+20000]   = fminf(fmaxf(a2*0.2f, 0.f), 1.f);
        g_proj[po+30000]   = fminf(fmaxf(a3*0.2f, 0.f), 1.f);
    } else {
        float4* v = (float4*)(g_vox0 + (size_t)cell*ZALL);
        float ah=0.f, allv=0.f, stv=0.f;
        const float4 z4 = make_float4(0.f,0.f,0.f,0.f);
        #pragma unroll
        for (int half=0; half<2; half++) {
            float4 r[6];
            #pragma unroll
            for (int q=0; q<6; q++) r[q] = v[half*6 + q];
            #pragma unroll
            for (int q=0; q<6; q++) v[half*6 + q] = z4;
            #pragma unroll
            for (int q=0; q<6; q++) {
                float vals[4] = {r[q].x, r[q].y, r[q].z, r[q].w};
                #pragma unroll
                for (int k=0;k<4;k++) {
                    int z = half*24 + q*4 + k;
                    float qq = rintf(vals[k]);
                    allv += qq;
                    if (z>=ZLO && z<ZHI) ah += qq;
                    if (z>=20 && z<25) stv += qq;
                }
            }
        }
        size_t po = (size_t)b*19*10000 + (size_t)y*100 + x;
        g_proj[po]            = fminf(fmaxf(ah,  0.f),1.f);
        g_proj[po +  10000]   = fminf(fmaxf(allv,0.f),1.f);
        g_proj[po + 18*10000] = fminf(fmaxf(stv, 0.f),1.f);
    }
}

// ---------------- rot-sample helpers ----------------
struct Tap { int o0,o1,o2,o3; float w0,w1,w2,w3; };

__device__ __forceinline__ bool rot_taps(float cc, float ss, int ir, int jr, Tap& tp) {
    if (ir < 0 || ir >= 480 || jr < 0 || jr >= 480) return false;
    float gxp = ((float)jr + 0.5f)*(1.0f/240.0f) - 1.0f;
    float gyp = ((float)ir + 0.5f)*(1.0f/240.0f) - 1.0f;
    float fxp = (cc*gxp - ss*gyp + 1.0f)*239.5f;
    float fyp = (ss*gxp + cc*gyp + 1.0f)*239.5f;
    float xf = floorf(fxp), yf = floorf(fyp);
    int xp = (int)xf, yp = (int)yf;
    if (xp < 189 || xp > 289 || yp < 239 || yp > 339) return false;
    float ux1 = fxp - xf, ux0 = 1.0f - ux1;
    float uy1 = fyp - yf, uy0 = 1.0f - uy1;
    int xs0 = xp-190, xs1 = xp-189, ys0 = yp-240, ys1 = yp-239;
    bool vx0 = (xs0>=0 && xs0<100), vx1 = (xs1>=0 && xs1<100);
    bool vy0 = (ys0>=0 && ys0<100), vy1 = (ys1>=0 && ys1<100);
    tp.w0 = (vx0&&vy0) ? ux0*uy0 : 0.0f;
    tp.w1 = (vx1&&vy0) ? ux1*uy0 : 0.0f;
    tp.w2 = (vx0&&vy1) ? ux0*uy1 : 0.0f;
    tp.w3 = (vx1&&vy1) ? ux1*uy1 : 0.0f;
    tp.o0 = (vx0&&vy0) ? ys0*100+xs0 : 0;
    tp.o1 = (vx1&&vy0) ? ys0*100+xs1 : 0;
    tp.o2 = (vx0&&vy1) ? ys1*100+xs0 : 0;
    tp.o3 = (vx1&&vy1) ? ys1*100+xs1 : 0;
    return true;
}

// per-pixel translation setup: returns true if any tap is in-box
__device__ __forceinline__ bool pix_taps(float cc, float ss, float stx, float sty,
                                         int i, int j,
                                         Tap ct[4], bool cin[4], float cw[4]) {
    float gx = ((float)j + 0.5f)*(1.0f/240.0f) - 1.0f + stx;
    float gy = ((float)i + 0.5f)*(1.0f/240.0f) - 1.0f + sty;
    float fx = (gx + 1.0f)*239.5f;
    float fy = (gy + 1.0f)*239.5f;
    float x0f = floorf(fx), y0f = floorf(fy);
    int x0 = (int)x0f, y0 = (int)y0f;
    float wx1 = fx - x0f, wx0 = 1.0f - wx1;
    float wy1 = fy - y0f, wy0 = 1.0f - wy1;
    cin[0] = rot_taps(cc, ss, y0,   x0,   ct[0]);
    cin[1] = rot_taps(cc, ss, y0,   x0+1, ct[1]);
    cin[2] = rot_taps(cc, ss, y0+1, x0,   ct[2]);
    cin[3] = rot_taps(cc, ss, y0+1, x0+1, ct[3]);
    cw[0] = wx0*wy0; cw[1] = wx1*wy0; cw[2] = wx0*wy1; cw[3] = wx1*wy1;
    return cin[0] | cin[1] | cin[2] | cin[3];
}

__device__ __forceinline__ float gather_plane(const float* pp, const Tap ct[4],
                                              const bool cin[4], const float cw[4]) {
    float acc = 0.0f;
    #pragma unroll
    for (int k=0;k<4;k++) {
        if (!cin[k]) continue;
        acc += cw[k]*(ct[k].w0*pp[ct[k].o0] + ct[k].w1*pp[ct[k].o1] +
                      ct[k].w2*pp[ct[k].o2] + ct[k].w3*pp[ct[k].o3]);
    }
    return acc;
}

// t0 (translated plane 0) value at arbitrary pixel; -INF outside image (maxpool pad)
__device__ __forceinline__ float t0_at(const float* pb, float cc, float ss,
                                       float stx, float sty, int i, int j) {
    if (i < 0 || i >= 480 || j < 0 || j >= 480) return -INFINITY;
    Tap ct[4]; bool cin[4]; float cw[4];
    if (!pix_taps(cc, ss, stx, sty, i, j, ct, cin, cw)) return 0.0f;
    return gather_plane(pb, ct, cin, cw);
}

// ---------------- K3: fused warp + maxpool + diff + mask + merge ----------------
__global__ void __launch_bounds__(256) k_out(const float* __restrict__ maps_last,
                                             const float* __restrict__ eve,
                                             float* __restrict__ out_t,
                                             float* __restrict__ out_p,
                                             float* __restrict__ out_s) {
    __shared__ float t0s[18][18];

    int tx = threadIdx.x & 15, ty = threadIdx.x >> 4;
    int b  = blockIdx.z;
    int bi0 = blockIdx.y*16, bj0 = blockIdx.x*16;
    int i = bi0 + ty, j = bj0 + tx;

    float cc  = g_par[b*4+0], ss  = g_par[b*4+1];
    float stx = g_par[b*4+2], sty = g_par[b*4+3];
    const float* pb = g_proj + (size_t)b*19*10000;

    // own pixel taps + t0
    Tap ct[4]; bool cin[4]; float cw[4];
    bool inbox = pix_taps(cc, ss, stx, sty, i, j, ct, cin, cw);
    float t0 = inbox ? gather_plane(pb, ct, cin, cw) : 0.0f;
    t0s[ty+1][tx+1] = t0;

    // halo: 68 perimeter cells
    int idx = threadIdx.x;
    if (idx < 68) {
        int hy, hx;
        if (idx < 18)      { hy = 0;  hx = idx; }
        else if (idx < 36) { hy = 17; hx = idx - 18; }
        else { int k = idx - 36; hy = 1 + (k >> 1); hx = (k & 1) * 17; }
        t0s[hy][hx] = t0_at(pb, cc, ss, stx, sty, bi0 - 1 + hy, bj0 - 1 + hx);
    }
    __syncthreads();

    // 3x3 maxpool
    float mp = t0s[ty][tx];
    mp = fmaxf(mp, t0s[ty][tx+1]);   mp = fmaxf(mp, t0s[ty][tx+2]);
    mp = fmaxf(mp, t0s[ty+1][tx]);   mp = fmaxf(mp, t0s[ty+1][tx+1]); mp = fmaxf(mp, t0s[ty+1][tx+2]);
    mp = fmaxf(mp, t0s[ty+2][tx]);   mp = fmaxf(mp, t0s[ty+2][tx+1]); mp = fmaxf(mp, t0s[ty+2][tx+2]);

    size_t pix = (size_t)i*480 + j;
    size_t ob  = (size_t)b*20*NM + pix;
    const float* ml = maps_last + ob;
    bool eve0 = (eve[b] == 0.0f);

    float mask = 1.0f;
    if (b == 0) {
        float dy = (float)i - (float)g_sxy[1] + 0.5f;
        float dx = (float)j - (float)g_sxy[0] + 0.5f;
        mask = (dy*dy + dx*dx <= 900.0f) ? 1.0f : 0.0f;
    }

    if (!inbox) {
        // t=0 everywhere; mp>=0 so dth/dsth can't fire (t1=0)
        #pragma unroll
        for (int c=0;c<20;c++) {
            float m = fmaxf(ml[(size_t)c*NM], 0.0f);
            out_t[ob + (size_t)c*NM] = 0.0f;
            out_p[ob + (size_t)c*NM] = m;
            out_s[ob + (size_t)c*NM] = m;
        }
        return;
    }

    // gather remaining planes 1..18
    float t1    = gather_plane(pb + 10000, ct, cin, cw);
    float tst   = gather_plane(pb + 18*10000, ct, cin, cw);   // stair plane
    bool dth  = (t1 - mp) > 0.8f;
    float ts0 = tst * mask;
    float ts1 = (b == 0) ? t1*mask : t1;
    bool dsth = (ts1 - ts0) > 0.8f;

    float ml0 = ml[0], ml1 = ml[(size_t)NM];
    out_t[ob]              = t0;
    out_t[ob + (size_t)NM] = t1;
    out_p[ob]              = (eve0 && dth)  ? 0.0f : fmaxf(ml0, t0);
    out_p[ob + (size_t)NM] = fmaxf(ml1, t1);
    out_s[ob]              = (eve0 && dsth) ? 0.0f : fmaxf(ml0, ts0);
    out_s[ob + (size_t)NM] = fmaxf(ml1, ts1);

    // channels 2,3 always zero in agent_view
    #pragma unroll
    for (int c=2;c<4;c++) {
        float m = fmaxf(ml[(size_t)c*NM], 0.0f);
        out_t[ob + (size_t)c*NM] = 0.0f;
        out_p[ob + (size_t)c*NM] = m;
        out_s[ob + (size_t)c*NM] = m;
    }
    // sem channels 4..19 from planes 2..17
    #pragma unroll
    for (int p=2;p<=17;p++) {
        int c = p + 2;
        float acc = gather_plane(pb + (size_t)p*10000, ct, cin, cw);
        float m = fmaxf(ml[(size_t)c*NM], acc);
        out_t[ob + (size_t)c*NM] = acc;
        out_p[ob + (size_t)c*NM] = m;
        out_s[ob + (size_t)c*NM] = m;
    }
}

// ---------------- launch ----------------
extern "C" void kernel_launch(void* const* d_in, const int* in_sizes, int n_in,
                              void* d_out, int out_size) {
    const float* obs        = (const float*)d_in[0];
    const float* pose_obs   = (const float*)d_in[1];
    const float* maps_last  = (const float*)d_in[2];
    const float* poses_last = (const float*)d_in[3];
    const float* eve        = (const float*)d_in[4];
    float* out   = (float*)d_out;
    float* out_p = out + (size_t)N1;
    float* out_s = out + (size_t)2*N1;

    float camf = (float)(320.0 / tan(39.5 * 3.14159265358979323846 / 180.0));

    k_pose <<<1, 8>>>(pose_obs, poses_last, out + (size_t)3*N1);
    k_splat<<<(8*240*320 + 255)/256, 256>>>(obs, eve, camf);
    k_proj <<<(5*NCELL + 255)/256, 256>>>();
    dim3 grid(30, 30, 8), blk(256);
    k_out  <<<grid, blk>>>(maps_last, eve, out, out_p, out_s);
}

// round 13
// speedup vs baseline: 1.3538x; 1.3538x over previous
#include <cuda_runtime.h>
#include <math.h>
#include <stdint.h>

// ---------------- constants ----------------
#define N_PIX (480*640)
#define NM    (480*480)          // one 480x480 plane
#define N1    (8*20*480*480)     // one full (bs,20,480,480) tensor
#define ZALL  48
#define ZLO   13                 // ah range [13,35)
#define ZHI   35
#define ZSEM  22                 // ZHI-ZLO

// ---------------- device scratch ----------------
__device__ float g_vox0[8*100*100*ZALL];        // [b][x][y][z]        15MB (ch0 counts)
__device__ float g_sem [8*100*100*ZSEM*16];     // [b][x][y][zr][ch]  113MB (sem feats)
__device__ float g_proj[8*19*100*100];          // [b][plane][y][x]; 0=map 1=exp 2..17=sem 18=stair
__device__ float g_par[32];                     // per b: cos, sin, stx, sty
__device__ int   g_sxy[2];                      // stair circle center (x, y), batch 0

// ---------------- vector reduction helper ----------------
__device__ __forceinline__ void red4(float* p, float a, float b, float c, float d) {
    asm volatile("red.global.add.v4.f32 [%0], {%1,%2,%3,%4};"
                 :: "l"(p), "f"(a), "f"(b), "f"(c), "f"(d) : "memory");
}

// ---------------- K0: poses + transform params ----------------
__global__ void k_pose(const float* __restrict__ pose_obs,
                       const float* __restrict__ poses_last,
                       float* __restrict__ out_pose) {
    int b = threadIdx.x;
    if (b >= 8) return;
    const float DEGf = 57.29577951308232f;
    float tr = poses_last[b*3+2] / DEGf;
    float s = sinf(tr), c = cosf(tr);
    float ny = poses_last[b*3+1] + pose_obs[b*3+0]*s + pose_obs[b*3+1]*c;
    float nx = poses_last[b*3+0] + pose_obs[b*3+0]*c - pose_obs[b*3+1]*s;
    float no = poses_last[b*3+2] + pose_obs[b*3+2]*DEGf;
    no = fmodf(no - 180.0f, 360.0f) + 180.0f;
    no = fmodf(no + 180.0f, 360.0f) - 180.0f;
    out_pose[b*3+0] = nx; out_pose[b*3+1] = ny; out_pose[b*3+2] = no;

    float stx = -(nx*100.0f/5.0f - 240.0f)/240.0f;
    float sty = -(ny*100.0f/5.0f - 240.0f)/240.0f;
    float st_t = (90.0f - no) * 0.017453292519943295f;
    g_par[b*4+0] = cosf(st_t);
    g_par[b*4+1] = sinf(st_t);
    g_par[b*4+2] = stx;
    g_par[b*4+3] = sty;
    if (b == 0) {
        int sy = (int)(ny*100.0f/5.0f); sy = min(max(sy,30),449);
        int sx = (int)(nx*100.0f/5.0f); sx = min(max(sx,30),449);
        g_sxy[0] = sx; g_sxy[1] = sy;
    }
}

// ---------------- K1: trilinear splat ----------------
__global__ void k_splat(const float* __restrict__ obs,
                        const float* __restrict__ eve, float camf) {
    int t = blockIdx.x*blockDim.x + threadIdx.x;
    if (t >= 8*240*320) return;
    int j = t % 320;
    int i = (t/320) % 240;
    int b = t / (320*240);
    const float* ob = obs + (size_t)b*20*N_PIX;

    float d = ob[(size_t)3*N_PIX + (size_t)(2*i)*640 + 2*j];
    float X = ((float)(2*j) - 319.5f) * d / camf;
    float Z = ((float)(479 - 2*i) - 239.5f) * d / camf;
    float th = eve[b] * 0.017453292519943295f;
    float ct = cosf(th), st = sinf(th);
    float Yr = ct*d - st*Z;
    float Zr = st*d + ct*Z + 88.0f;
    float Xs = X + 250.0f;
    float cx = (Xs/5.0f - 50.0f)/100.0f*2.0f;
    float cy = (Yr/5.0f - 50.0f)/100.0f*2.0f;
    float cz = (Zr/5.0f - 16.0f)/48.0f*2.0f;
    float pos[3] = { cx*50.0f+50.0f, cy*50.0f+50.0f, cz*24.0f+24.0f };
    const int gd[3] = {100,100,48};

    int   ip[3][2];
    float w [3][2];
    #pragma unroll
    for (int dd=0; dd<3; dd++) {
        float fl = floorf(pos[dd]);
        #pragma unroll
        for (int ix=0; ix<2; ix++) {
            float pix = fl + (float)ix;
            bool safe = (pix > 0.0f) && (pix < (float)gd[dd]);
            w[dd][ix]  = safe ? (1.0f - fabsf(pos[dd]-pix)) : 0.0f;
            ip[dd][ix] = safe ? (int)pix : 0;
        }
    }

    float fs[16];
    #pragma unroll
    for (int c=0;c<16;c++) {
        const float2* p0 = (const float2*)(ob + (size_t)(4+c)*N_PIX + (size_t)(2*i)*640 + 2*j);
        const float2* p1 = (const float2*)((const float*)p0 + 640);
        float2 a = *p0, bb = *p1;
        fs[c] = (a.x + a.y + bb.x + bb.y) * 0.25f;
    }

    #pragma unroll
    for (int a=0;a<2;a++)
    #pragma unroll
    for (int e=0;e<2;e++) {
        float w01 = w[0][a]*w[1][e];
        if (w01 == 0.0f) continue;
        size_t cell = ((size_t)b*100 + ip[0][a])*100 + ip[1][e];
        #pragma unroll
        for (int f=0;f<2;f++) {
            float ww = w01*w[2][f];
            if (ww == 0.0f) continue;
            int z = ip[2][f];
            atomicAdd(&g_vox0[cell*ZALL + z], ww);
            if (z >= ZLO && z < ZHI) {
                float* p = g_sem + (cell*ZSEM + (z-ZLO))*16;
                red4(p,    fs[0]*ww,  fs[1]*ww,  fs[2]*ww,  fs[3]*ww);
                red4(p+4,  fs[4]*ww,  fs[5]*ww,  fs[6]*ww,  fs[7]*ww);
                red4(p+8,  fs[8]*ww,  fs[9]*ww,  fs[10]*ww, fs[11]*ww);
                red4(p+12, fs[12]*ww, fs[13]*ww, fs[14]*ww, fs[15]*ww);
            }
        }
    }
}

// ---------------- K2a: ch0 projections (map/exp/stair) + re-zero ----------------
__global__ void __launch_bounds__(256) k_proj0() {
    int t = blockIdx.x*blockDim.x + threadIdx.x;
    if (t >= 8*100*100) return;
    int y = t % 100;
    int x = (t/100) % 100;
    int b = t / 10000;
    float4* v = (float4*)(g_vox0 + (size_t)t*ZALL);
    float ah=0.f, allv=0.f, stv=0.f;
    const float4 z4 = make_float4(0.f,0.f,0.f,0.f);
    #pragma unroll
    for (int half=0; half<2; half++) {
        float4 r[6];
        #pragma unroll
        for (int q=0; q<6; q++) r[q] = v[half*6 + q];
        #pragma unroll
        for (int q=0; q<6; q++) v[half*6 + q] = z4;
        #pragma unroll
        for (int q=0; q<6; q++) {
            float vals[4] = {r[q].x, r[q].y, r[q].z, r[q].w};
            #pragma unroll
            for (int k=0;k<4;k++) {
                int z = half*24 + q*4 + k;
                float qq = rintf(vals[k]);
                allv += qq;
                if (z>=ZLO && z<ZHI) ah += qq;
                if (z>=20 && z<25) stv += qq;
            }
        }
    }
    size_t po = (size_t)b*19*10000 + (size_t)y*100 + x;
    g_proj[po]            = fminf(fmaxf(ah,  0.f),1.f);
    g_proj[po +  10000]   = fminf(fmaxf(allv,0.f),1.f);
    g_proj[po + 18*10000] = fminf(fmaxf(stv, 0.f),1.f);
}

// ---------------- K2b: sem projections + re-zero (interleaved layout!) ----------------
__global__ void __launch_bounds__(256) k_projsem() {
    int t = blockIdx.x*blockDim.x + threadIdx.x;
    if (t >= 8*100*100*4) return;
    int g    = t & 3;              // channel group (4 ch each)
    int cell = t >> 2;             // b*10000 + x*100 + y
    int y = cell % 100;
    int x = (cell/100) % 100;
    int b = cell / 10000;
    float4* v = (float4*)(g_sem + (size_t)cell*ZSEM*16) + g;   // stride 4 float4 per z
    float a0=0.f, a1=0.f, a2=0.f, a3=0.f;
    const float4 z4 = make_float4(0.f,0.f,0.f,0.f);
    #pragma unroll
    for (int half=0; half<2; half++) {
        float4 r[11];
        #pragma unroll
        for (int z=0; z<11; z++) r[z] = v[(half*11 + z)*4];
        #pragma unroll
        for (int z=0; z<11; z++) v[(half*11 + z)*4] = z4;
        #pragma unroll
        for (int z=0; z<11; z++) {
            a0 += rintf(r[z].x);
            a1 += rintf(r[z].y);
            a2 += rintf(r[z].z);
            a3 += rintf(r[z].w);
        }
    }
    size_t po = (size_t)b*19*10000 + (size_t)(2 + g*4)*10000 + (size_t)y*100 + x;
    g_proj[po]         = fminf(fmaxf(a0*0.2f, 0.f), 1.f);
    g_proj[po+10000]   = fminf(fmaxf(a1*0.2f, 0.f), 1.f);
    g_proj[po+20000]   = fminf(fmaxf(a2*0.2f, 0.f), 1.f);
    g_proj[po+30000]   = fminf(fmaxf(a3*0.2f, 0.f), 1.f);
}

// ---------------- rot-sample helpers ----------------
struct Tap { int o0,o1,o2,o3; float w0,w1,w2,w3; };

__device__ __forceinline__ bool rot_taps(float cc, float ss, int ir, int jr, Tap& tp) {
    if (ir < 0 || ir >= 480 || jr < 0 || jr >= 480) return false;
    float gxp = ((float)jr + 0.5f)*(1.0f/240.0f) - 1.0f;
    float gyp = ((float)ir + 0.5f)*(1.0f/240.0f) - 1.0f;
    float fxp = (cc*gxp - ss*gyp + 1.0f)*239.5f;
    float fyp = (ss*gxp + cc*gyp + 1.0f)*239.5f;
    float xf = floorf(fxp), yf = floorf(fyp);
    int xp = (int)xf, yp = (int)yf;
    if (xp < 189 || xp > 289 || yp < 239 || yp > 339) return false;
    float ux1 = fxp - xf, ux0 = 1.0f - ux1;
    float uy1 = fyp - yf, uy0 = 1.0f - uy1;
    int xs0 = xp-190, xs1 = xp-189, ys0 = yp-240, ys1 = yp-239;
    bool vx0 = (xs0>=0 && xs0<100), vx1 = (xs1>=0 && xs1<100);
    bool vy0 = (ys0>=0 && ys0<100), vy1 = (ys1>=0 && ys1<100);
    tp.w0 = (vx0&&vy0) ? ux0*uy0 : 0.0f;
    tp.w1 = (vx1&&vy0) ? ux1*uy0 : 0.0f;
    tp.w2 = (vx0&&vy1) ? ux0*uy1 : 0.0f;
    tp.w3 = (vx1&&vy1) ? ux1*uy1 : 0.0f;
    tp.o0 = (vx0&&vy0) ? ys0*100+xs0 : 0;
    tp.o1 = (vx1&&vy0) ? ys0*100+xs1 : 0;
    tp.o2 = (vx0&&vy1) ? ys1*100+xs0 : 0;
    tp.o3 = (vx1&&vy1) ? ys1*100+xs1 : 0;
    return true;
}

// per-pixel translation setup: returns true if any tap is in-box
__device__ __forceinline__ bool pix_taps(float cc, float ss, float stx, float sty,
                                         int i, int j,
                                         Tap ct[4], bool cin[4], float cw[4]) {
    float gx = ((float)j + 0.5f)*(1.0f/240.0f) - 1.0f + stx;
    float gy = ((float)i + 0.5f)*(1.0f/240.0f) - 1.0f + sty;
    float fx = (gx + 1.0f)*239.5f;
    float fy = (gy + 1.0f)*239.5f;
    float x0f = floorf(fx), y0f = floorf(fy);
    int x0 = (int)x0f, y0 = (int)y0f;
    float wx1 = fx - x0f, wx0 = 1.0f - wx1;
    float wy1 = fy - y0f, wy0 = 1.0f - wy1;
    cin[0] = rot_taps(cc, ss, y0,   x0,   ct[0]);
    cin[1] = rot_taps(cc, ss, y0,   x0+1, ct[1]);
    cin[2] = rot_taps(cc, ss, y0+1, x0,   ct[2]);
    cin[3] = rot_taps(cc, ss, y0+1, x0+1, ct[3]);
    cw[0] = wx0*wy0; cw[1] = wx1*wy0; cw[2] = wx0*wy1; cw[3] = wx1*wy1;
    return cin[0] | cin[1] | cin[2] | cin[3];
}

__device__ __forceinline__ float gather_plane(const float* pp, const Tap ct[4],
                                              const bool cin[4], const float cw[4]) {
    float acc = 0.0f;
    #pragma unroll
    for (int k=0;k<4;k++) {
        if (!cin[k]) continue;
        acc += cw[k]*(ct[k].w0*pp[ct[k].o0] + ct[k].w1*pp[ct[k].o1] +
                      ct[k].w2*pp[ct[k].o2] + ct[k].w3*pp[ct[k].o3]);
    }
    return acc;
}

// t0 (translated plane 0) value at arbitrary pixel; -INF outside image (maxpool pad)
__device__ __forceinline__ float t0_at(const float* pb, float cc, float ss,
                                       float stx, float sty, int i, int j) {
    if (i < 0 || i >= 480 || j < 0 || j >= 480) return -INFINITY;
    Tap ct[4]; bool cin[4]; float cw[4];
    if (!pix_taps(cc, ss, stx, sty, i, j, ct, cin, cw)) return 0.0f;
    return gather_plane(pb, ct, cin, cw);
}

// gather via smem-cached composite taps (16 offsets + 16 weights per pixel)
__device__ __forceinline__ float gather_smem(const float* __restrict__ pp,
                                             const uint16_t* __restrict__ o,
                                             const float* __restrict__ w) {
    float acc = 0.0f;
    #pragma unroll
    for (int m=0;m<16;m++) acc += w[m]*pp[o[m]];
    return acc;
}

// ---------------- K3: fused warp + maxpool + diff + mask + merge (smem taps) ----------------
__global__ void __launch_bounds__(256) k_out(const float* __restrict__ maps_last,
                                             const float* __restrict__ eve,
                                             float* __restrict__ out_t,
                                             float* __restrict__ out_p,
                                             float* __restrict__ out_s) {
    __shared__ float t0s[18][18];
    __shared__ uint16_t soff[256][16];
    __shared__ float    swt [256][16];

    int tid = threadIdx.x;
    int tx = tid & 15, ty = tid >> 4;
    int b  = blockIdx.z;
    int bi0 = blockIdx.y*16, bj0 = blockIdx.x*16;
    int i = bi0 + ty, j = bj0 + tx;

    float cc  = g_par[b*4+0], ss  = g_par[b*4+1];
    float stx = g_par[b*4+2], sty = g_par[b*4+3];
    const float* pb = g_proj + (size_t)b*19*10000;

    bool inbox;
    {   // taps scope: registers die after composing into smem
        Tap ct[4]; bool cin[4]; float cw[4];
        inbox = pix_taps(cc, ss, stx, sty, i, j, ct, cin, cw);
        if (inbox) {
            #pragma unroll
            for (int k=0;k<4;k++) {
                bool v = cin[k];
                soff[tid][4*k+0] = v ? (uint16_t)ct[k].o0 : 0;
                soff[tid][4*k+1] = v ? (uint16_t)ct[k].o1 : 0;
                soff[tid][4*k+2] = v ? (uint16_t)ct[k].o2 : 0;
                soff[tid][4*k+3] = v ? (uint16_t)ct[k].o3 : 0;
                swt [tid][4*k+0] = v ? cw[k]*ct[k].w0 : 0.0f;
                swt [tid][4*k+1] = v ? cw[k]*ct[k].w1 : 0.0f;
                swt [tid][4*k+2] = v ? cw[k]*ct[k].w2 : 0.0f;
                swt [tid][4*k+3] = v ? cw[k]*ct[k].w3 : 0.0f;
            }
        }
    }
    // own t0 (same-thread smem RAW needs no barrier)
    float t0 = inbox ? gather_smem(pb, soff[tid], swt[tid]) : 0.0f;
    t0s[ty+1][tx+1] = t0;

    // halo: 68 perimeter cells (full recompute, short register lifetime)
    if (tid < 68) {
        int hy, hx;
        if (tid < 18)      { hy = 0;  hx = tid; }
        else if (tid < 36) { hy = 17; hx = tid - 18; }
        else { int k = tid - 36; hy = 1 + (k >> 1); hx = (k & 1) * 17; }
        t0s[hy][hx] = t0_at(pb, cc, ss, stx, sty, bi0 - 1 + hy, bj0 - 1 + hx);
    }
    __syncthreads();

    // 3x3 maxpool
    float mp = t0s[ty][tx];
    mp = fmaxf(mp, t0s[ty][tx+1]);   mp = fmaxf(mp, t0s[ty][tx+2]);
    mp = fmaxf(mp, t0s[ty+1][tx]);   mp = fmaxf(mp, t0s[ty+1][tx+1]); mp = fmaxf(mp, t0s[ty+1][tx+2]);
    mp = fmaxf(mp, t0s[ty+2][tx]);   mp = fmaxf(mp, t0s[ty+2][tx+1]); mp = fmaxf(mp, t0s[ty+2][tx+2]);

    size_t pix = (size_t)i*480 + j;
    size_t ob  = (size_t)b*20*NM + pix;
    const float* ml = maps_last + ob;
    bool eve0 = (eve[b] == 0.0f);

    float mask = 1.0f;
    if (b == 0) {
        float dy = (float)i - (float)g_sxy[1] + 0.5f;
        float dx = (float)j - (float)g_sxy[0] + 0.5f;
        mask = (dy*dy + dx*dx <= 900.0f) ? 1.0f : 0.0f;
    }

    if (!inbox) {
        // t=0 everywhere; mp>=0 so dth/dsth can't fire (t1=0)
        #pragma unroll
        for (int c=0;c<20;c++) {
            float m = fmaxf(ml[(size_t)c*NM], 0.0f);
            out_t[ob + (size_t)c*NM] = 0.0f;
            out_p[ob + (size_t)c*NM] = m;
            out_s[ob + (size_t)c*NM] = m;
        }
        return;
    }

    const uint16_t* myo = soff[tid];
    const float*    myw = swt[tid];

    float t1    = gather_smem(pb + 10000,    myo, myw);
    float tst   = gather_smem(pb + 18*10000, myo, myw);   // stair plane
    bool dth  = (t1 - mp) > 0.8f;
    float ts0 = tst * mask;
    float ts1 = (b == 0) ? t1*mask : t1;
    bool dsth = (ts1 - ts0) > 0.8f;

    float ml0 = ml[0], ml1 = ml[(size_t)NM];
    out_t[ob]              = t0;
    out_t[ob + (size_t)NM] = t1;
    out_p[ob]              = (eve0 && dth)  ? 0.0f : fmaxf(ml0, t0);
    out_p[ob + (size_t)NM] = fmaxf(ml1, t1);
    out_s[ob]              = (eve0 && dsth) ? 0.0f : fmaxf(ml0, ts0);
    out_s[ob + (size_t)NM] = fmaxf(ml1, ts1);

    // channels 2,3 always zero in agent_view
    #pragma unroll
    for (int c=2;c<4;c++) {
        float m = fmaxf(ml[(size_t)c*NM], 0.0f);
        out_t[ob + (size_t)c*NM] = 0.0f;
        out_p[ob + (size_t)c*NM] = m;
        out_s[ob + (size_t)c*NM] = m;
    }
    // sem channels 4..19 from planes 2..17
    #pragma unroll 2
    for (int p=2;p<=17;p++) {
        int c = p + 2;
        float acc = gather_smem(pb + (size_t)p*10000, myo, myw);
        float m = fmaxf(ml[(size_t)c*NM], acc);
        out_t[ob + (size_t)c*NM] = acc;
        out_p[ob + (size_t)c*NM] = m;
        out_s[ob + (size_t)c*NM] = m;
    }
}

// ---------------- launch ----------------
extern "C" void kernel_launch(void* const* d_in, const int* in_sizes, int n_in,
                              void* d_out, int out_size) {
    const float* obs        = (const float*)d_in[0];
    const float* pose_obs   = (const float*)d_in[1];
    const float* maps_last  = (const float*)d_in[2];
    const float* poses_last = (const float*)d_in[3];
    const float* eve        = (const float*)d_in[4];
    float* out   = (float*)d_out;
    float* out_p = out + (size_t)N1;
    float* out_s = out + (size_t)2*N1;

    float camf = (float)(320.0 / tan(39.5 * 3.14159265358979323846 / 180.0));

    k_pose   <<<1, 8>>>(pose_obs, poses_last, out + (size_t)3*N1);
    k_splat  <<<(8*240*320 + 255)/256, 256>>>(obs, eve, camf);
    k_proj0  <<<(8*100*100 + 255)/256, 256>>>();
    k_projsem<<<(8*100*100*4 + 255)/256, 256>>>();
    dim3 grid(30, 30, 8), blk(256);
    k_out    <<<grid, blk>>>(maps_last, eve, out, out_p, out_s);
}

// round 14
// speedup vs baseline: 1.3945x; 1.0301x over previous
#include <cuda_runtime.h>
#include <math.h>
#include <stdint.h>

// ---------------- constants ----------------
#define N_PIX (480*640)
#define NM    (480*480)          // one 480x480 plane
#define N1    (8*20*480*480)     // one full (bs,20,480,480) tensor
#define ZALL  48
#define ZLO   13                 // ah range [13,35)
#define ZHI   35
#define ZSEM  22                 // ZHI-ZLO
#define NSEM_T (8*100*100*4)     // projsem thread count (320000 = 1250 blocks of 256)

// ---------------- device scratch ----------------
__device__ float g_vox0[8*100*100*ZALL];        // [b][x][y][z]        15MB (ch0 counts)
__device__ float g_sem [8*100*100*ZSEM*16];     // [b][x][y][zr][ch]  113MB (sem feats)
__device__ float g_proj[8*19*100*100];          // [b][plane][y][x]; 0=map 1=exp 2..17=sem 18=stair
__device__ float g_par[32];                     // per b: cos, sin, stx, sty
__device__ int   g_sxy[2];                      // stair circle center (x, y), batch 0

// ---------------- vector reduction helper ----------------
__device__ __forceinline__ void red4(float* p, float a, float b, float c, float d) {
    asm volatile("red.global.add.v4.f32 [%0], {%1,%2,%3,%4};"
                 :: "l"(p), "f"(a), "f"(b), "f"(c), "f"(d) : "memory");
}

// ---------------- K0: poses + transform params ----------------
__global__ void k_pose(const float* __restrict__ pose_obs,
                       const float* __restrict__ poses_last,
                       float* __restrict__ out_pose) {
    int b = threadIdx.x;
    if (b >= 8) return;
    const float DEGf = 57.29577951308232f;
    float tr = poses_last[b*3+2] / DEGf;
    float s = sinf(tr), c = cosf(tr);
    float ny = poses_last[b*3+1] + pose_obs[b*3+0]*s + pose_obs[b*3+1]*c;
    float nx = poses_last[b*3+0] + pose_obs[b*3+0]*c - pose_obs[b*3+1]*s;
    float no = poses_last[b*3+2] + pose_obs[b*3+2]*DEGf;
    no = fmodf(no - 180.0f, 360.0f) + 180.0f;
    no = fmodf(no + 180.0f, 360.0f) - 180.0f;
    out_pose[b*3+0] = nx; out_pose[b*3+1] = ny; out_pose[b*3+2] = no;

    float stx = -(nx*100.0f/5.0f - 240.0f)/240.0f;
    float sty = -(ny*100.0f/5.0f - 240.0f)/240.0f;
    float st_t = (90.0f - no) * 0.017453292519943295f;
    g_par[b*4+0] = cosf(st_t);
    g_par[b*4+1] = sinf(st_t);
    g_par[b*4+2] = stx;
    g_par[b*4+3] = sty;
    if (b == 0) {
        int sy = (int)(ny*100.0f/5.0f); sy = min(max(sy,30),449);
        int sx = (int)(nx*100.0f/5.0f); sx = min(max(sx,30),449);
        g_sxy[0] = sx; g_sxy[1] = sy;
    }
}

// ---------------- K1: trilinear splat ----------------
__global__ void k_splat(const float* __restrict__ obs,
                        const float* __restrict__ eve, float camf) {
    int t = blockIdx.x*blockDim.x + threadIdx.x;
    if (t >= 8*240*320) return;
    int j = t % 320;
    int i = (t/320) % 240;
    int b = t / (320*240);
    const float* ob = obs + (size_t)b*20*N_PIX;

    float d = ob[(size_t)3*N_PIX + (size_t)(2*i)*640 + 2*j];
    float X = ((float)(2*j) - 319.5f) * d / camf;
    float Z = ((float)(479 - 2*i) - 239.5f) * d / camf;
    float th = eve[b] * 0.017453292519943295f;
    float ct = cosf(th), st = sinf(th);
    float Yr = ct*d - st*Z;
    float Zr = st*d + ct*Z + 88.0f;
    float Xs = X + 250.0f;
    float cx = (Xs/5.0f - 50.0f)/100.0f*2.0f;
    float cy = (Yr/5.0f - 50.0f)/100.0f*2.0f;
    float cz = (Zr/5.0f - 16.0f)/48.0f*2.0f;
    float pos[3] = { cx*50.0f+50.0f, cy*50.0f+50.0f, cz*24.0f+24.0f };
    const int gd[3] = {100,100,48};

    int   ip[3][2];
    float w [3][2];
    #pragma unroll
    for (int dd=0; dd<3; dd++) {
        float fl = floorf(pos[dd]);
        #pragma unroll
        for (int ix=0; ix<2; ix++) {
            float pix = fl + (float)ix;
            bool safe = (pix > 0.0f) && (pix < (float)gd[dd]);
            w[dd][ix]  = safe ? (1.0f - fabsf(pos[dd]-pix)) : 0.0f;
            ip[dd][ix] = safe ? (int)pix : 0;
        }
    }

    float fs[16];
    #pragma unroll
    for (int c=0;c<16;c++) {
        const float2* p0 = (const float2*)(ob + (size_t)(4+c)*N_PIX + (size_t)(2*i)*640 + 2*j);
        const float2* p1 = (const float2*)((const float*)p0 + 640);
        float2 a = *p0, bb = *p1;
        fs[c] = (a.x + a.y + bb.x + bb.y) * 0.25f;
    }

    #pragma unroll
    for (int a=0;a<2;a++)
    #pragma unroll
    for (int e=0;e<2;e++) {
        float w01 = w[0][a]*w[1][e];
        if (w01 == 0.0f) continue;
        size_t cell = ((size_t)b*100 + ip[0][a])*100 + ip[1][e];
        #pragma unroll
        for (int f=0;f<2;f++) {
            float ww = w01*w[2][f];
            if (ww == 0.0f) continue;
            int z = ip[2][f];
            atomicAdd(&g_vox0[cell*ZALL + z], ww);
            if (z >= ZLO && z < ZHI) {
                float* p = g_sem + (cell*ZSEM + (z-ZLO))*16;
                red4(p,    fs[0]*ww,  fs[1]*ww,  fs[2]*ww,  fs[3]*ww);
                red4(p+4,  fs[4]*ww,  fs[5]*ww,  fs[6]*ww,  fs[7]*ww);
                red4(p+8,  fs[8]*ww,  fs[9]*ww,  fs[10]*ww, fs[11]*ww);
                red4(p+12, fs[12]*ww, fs[13]*ww, fs[14]*ww, fs[15]*ww);
            }
        }
    }
}

// ---------------- K2: fused projections + re-zero ----------------
// t < NSEM_T: sem groups with R7's exact interleaved indexing (g = t&3, cell = t>>2).
// t >= NSEM_T: vox0 ch0 projection, cell = t - NSEM_T.
// NSEM_T = 320000 = 1250*256, so the two ranges never share a block.
__global__ void __launch_bounds__(256) k_projall() {
    int t = blockIdx.x*blockDim.x + threadIdx.x;
    if (t < NSEM_T) {
        int g    = t & 3;              // channel group (4 ch each)
        int cell = t >> 2;             // b*10000 + x*100 + y
        int y = cell % 100;
        int x = (cell/100) % 100;
        int b = cell / 10000;
        float4* v = (float4*)(g_sem + (size_t)cell*ZSEM*16) + g;   // stride 4 float4 per z
        float a0=0.f, a1=0.f, a2=0.f, a3=0.f;
        const float4 z4 = make_float4(0.f,0.f,0.f,0.f);
        #pragma unroll
        for (int half=0; half<2; half++) {
            float4 r[11];
            #pragma unroll
            for (int z=0; z<11; z++) r[z] = v[(half*11 + z)*4];
            #pragma unroll
            for (int z=0; z<11; z++) v[(half*11 + z)*4] = z4;
            #pragma unroll
            for (int z=0; z<11; z++) {
                a0 += rintf(r[z].x);
                a1 += rintf(r[z].y);
                a2 += rintf(r[z].z);
                a3 += rintf(r[z].w);
            }
        }
        size_t po = (size_t)b*19*10000 + (size_t)(2 + g*4)*10000 + (size_t)y*100 + x;
        g_proj[po]         = fminf(fmaxf(a0*0.2f, 0.f), 1.f);
        g_proj[po+10000]   = fminf(fmaxf(a1*0.2f, 0.f), 1.f);
        g_proj[po+20000]   = fminf(fmaxf(a2*0.2f, 0.f), 1.f);
        g_proj[po+30000]   = fminf(fmaxf(a3*0.2f, 0.f), 1.f);
    } else {
        int cell = t - NSEM_T;
        if (cell >= 8*100*100) return;
        int y = cell % 100;
        int x = (cell/100) % 100;
        int b = cell / 10000;
        float4* v = (float4*)(g_vox0 + (size_t)cell*ZALL);
        float ah=0.f, allv=0.f, stv=0.f;
        const float4 z4 = make_float4(0.f,0.f,0.f,0.f);
        #pragma unroll
        for (int half=0; half<2; half++) {
            float4 r[6];
            #pragma unroll
            for (int q=0; q<6; q++) r[q] = v[half*6 + q];
            #pragma unroll
            for (int q=0; q<6; q++) v[half*6 + q] = z4;
            #pragma unroll
            for (int q=0; q<6; q++) {
                float vals[4] = {r[q].x, r[q].y, r[q].z, r[q].w};
                #pragma unroll
                for (int k=0;k<4;k++) {
                    int z = half*24 + q*4 + k;
                    float qq = rintf(vals[k]);
                    allv += qq;
                    if (z>=ZLO && z<ZHI) ah += qq;
                    if (z>=20 && z<25) stv += qq;
                }
            }
        }
        size_t po = (size_t)b*19*10000 + (size_t)y*100 + x;
        g_proj[po]            = fminf(fmaxf(ah,  0.f),1.f);
        g_proj[po +  10000]   = fminf(fmaxf(allv,0.f),1.f);
        g_proj[po + 18*10000] = fminf(fmaxf(stv, 0.f),1.f);
    }
}

// ---------------- rot-sample helpers ----------------
struct Tap { int o0,o1,o2,o3; float w0,w1,w2,w3; };

__device__ __forceinline__ bool rot_taps(float cc, float ss, int ir, int jr, Tap& tp) {
    if (ir < 0 || ir >= 480 || jr < 0 || jr >= 480) return false;
    float gxp = ((float)jr + 0.5f)*(1.0f/240.0f) - 1.0f;
    float gyp = ((float)ir + 0.5f)*(1.0f/240.0f) - 1.0f;
    float fxp = (cc*gxp - ss*gyp + 1.0f)*239.5f;
    float fyp = (ss*gxp + cc*gyp + 1.0f)*239.5f;
    float xf = floorf(fxp), yf = floorf(fyp);
    int xp = (int)xf, yp = (int)yf;
    if (xp < 189 || xp > 289 || yp < 239 || yp > 339) return false;
    float ux1 = fxp - xf, ux0 = 1.0f - ux1;
    float uy1 = fyp - yf, uy0 = 1.0f - uy1;
    int xs0 = xp-190, xs1 = xp-189, ys0 = yp-240, ys1 = yp-239;
    bool vx0 = (xs0>=0 && xs0<100), vx1 = (xs1>=0 && xs1<100);
    bool vy0 = (ys0>=0 && ys0<100), vy1 = (ys1>=0 && ys1<100);
    tp.w0 = (vx0&&vy0) ? ux0*uy0 : 0.0f;
    tp.w1 = (vx1&&vy0) ? ux1*uy0 : 0.0f;
    tp.w2 = (vx0&&vy1) ? ux0*uy1 : 0.0f;
    tp.w3 = (vx1&&vy1) ? ux1*uy1 : 0.0f;
    tp.o0 = (vx0&&vy0) ? ys0*100+xs0 : 0;
    tp.o1 = (vx1&&vy0) ? ys0*100+xs1 : 0;
    tp.o2 = (vx0&&vy1) ? ys1*100+xs0 : 0;
    tp.o3 = (vx1&&vy1) ? ys1*100+xs1 : 0;
    return true;
}

// per-pixel translation setup: returns true if any tap is in-box
__device__ __forceinline__ bool pix_taps(float cc, float ss, float stx, float sty,
                                         int i, int j,
                                         Tap ct[4], bool cin[4], float cw[4]) {
    float gx = ((float)j + 0.5f)*(1.0f/240.0f) - 1.0f + stx;
    float gy = ((float)i + 0.5f)*(1.0f/240.0f) - 1.0f + sty;
    float fx = (gx + 1.0f)*239.5f;
    float fy = (gy + 1.0f)*239.5f;
    float x0f = floorf(fx), y0f = floorf(fy);
    int x0 = (int)x0f, y0 = (int)y0f;
    float wx1 = fx - x0f, wx0 = 1.0f - wx1;
    float wy1 = fy - y0f, wy0 = 1.0f - wy1;
    cin[0] = rot_taps(cc, ss, y0,   x0,   ct[0]);
    cin[1] = rot_taps(cc, ss, y0,   x0+1, ct[1]);
    cin[2] = rot_taps(cc, ss, y0+1, x0,   ct[2]);
    cin[3] = rot_taps(cc, ss, y0+1, x0+1, ct[3]);
    cw[0] = wx0*wy0; cw[1] = wx1*wy0; cw[2] = wx0*wy1; cw[3] = wx1*wy1;
    return cin[0] | cin[1] | cin[2] | cin[3];
}

__device__ __forceinline__ float gather_plane(const float* pp, const Tap ct[4],
                                              const bool cin[4], const float cw[4]) {
    float acc = 0.0f;
    #pragma unroll
    for (int k=0;k<4;k++) {
        if (!cin[k]) continue;
        acc += cw[k]*(ct[k].w0*pp[ct[k].o0] + ct[k].w1*pp[ct[k].o1] +
                      ct[k].w2*pp[ct[k].o2] + ct[k].w3*pp[ct[k].o3]);
    }
    return acc;
}

// t0 (translated plane 0) value at arbitrary pixel; -INF outside image (maxpool pad)
__device__ __forceinline__ float t0_at(const float* pb, float cc, float ss,
                                       float stx, float sty, int i, int j) {
    if (i < 0 || i >= 480 || j < 0 || j >= 480) return -INFINITY;
    Tap ct[4]; bool cin[4]; float cw[4];
    if (!pix_taps(cc, ss, stx, sty, i, j, ct, cin, cw)) return 0.0f;
    return gather_plane(pb, ct, cin, cw);
}

// gather via smem-cached composite taps (16 offsets + 16 weights per pixel)
__device__ __forceinline__ float gather_smem(const float* __restrict__ pp,
                                             const uint16_t* __restrict__ o,
                                             const float* __restrict__ w) {
    float acc = 0.0f;
    #pragma unroll
    for (int m=0;m<16;m++) acc += w[m]*pp[o[m]];
    return acc;
}

// ---------------- K3: fused warp + maxpool + diff + mask + merge (smem taps) ----------------
__global__ void __launch_bounds__(256) k_out(const float* __restrict__ maps_last,
                                             const float* __restrict__ eve,
                                             float* __restrict__ out_t,
                                             float* __restrict__ out_p,
                                             float* __restrict__ out_s) {
    __shared__ float t0s[18][18];
    __shared__ uint16_t soff[256][16];
    __shared__ float    swt [256][16];

    int tid = threadIdx.x;
    int tx = tid & 15, ty = tid >> 4;
    int b  = blockIdx.z;
    int bi0 = blockIdx.y*16, bj0 = blockIdx.x*16;
    int i = bi0 + ty, j = bj0 + tx;

    float cc  = g_par[b*4+0], ss  = g_par[b*4+1];
    float stx = g_par[b*4+2], sty = g_par[b*4+3];
    const float* pb = g_proj + (size_t)b*19*10000;

    bool inbox;
    {   // taps scope: registers die after composing into smem
        Tap ct[4]; bool cin[4]; float cw[4];
        inbox = pix_taps(cc, ss, stx, sty, i, j, ct, cin, cw);
        if (inbox) {
            #pragma unroll
            for (int k=0;k<4;k++) {
                bool v = cin[k];
                soff[tid][4*k+0] = v ? (uint16_t)ct[k].o0 : 0;
                soff[tid][4*k+1] = v ? (uint16_t)ct[k].o1 : 0;
                soff[tid][4*k+2] = v ? (uint16_t)ct[k].o2 : 0;
                soff[tid][4*k+3] = v ? (uint16_t)ct[k].o3 : 0;
                swt [tid][4*k+0] = v ? cw[k]*ct[k].w0 : 0.0f;
                swt [tid][4*k+1] = v ? cw[k]*ct[k].w1 : 0.0f;
                swt [tid][4*k+2] = v ? cw[k]*ct[k].w2 : 0.0f;
                swt [tid][4*k+3] = v ? cw[k]*ct[k].w3 : 0.0f;
            }
        }
    }
    // own t0 (same-thread smem RAW needs no barrier)
    float t0 = inbox ? gather_smem(pb, soff[tid], swt[tid]) : 0.0f;
    t0s[ty+1][tx+1] = t0;

    // halo: 68 perimeter cells (full recompute, short register lifetime)
    if (tid < 68) {
        int hy, hx;
        if (tid < 18)      { hy = 0;  hx = tid; }
        else if (tid < 36) { hy = 17; hx = tid - 18; }
        else { int k = tid - 36; hy = 1 + (k >> 1); hx = (k & 1) * 17; }
        t0s[hy][hx] = t0_at(pb, cc, ss, stx, sty, bi0 - 1 + hy, bj0 - 1 + hx);
    }
    __syncthreads();

    // 3x3 maxpool
    float mp = t0s[ty][tx];
    mp = fmaxf(mp, t0s[ty][tx+1]);   mp = fmaxf(mp, t0s[ty][tx+2]);
    mp = fmaxf(mp, t0s[ty+1][tx]);   mp = fmaxf(mp, t0s[ty+1][tx+1]); mp = fmaxf(mp, t0s[ty+1][tx+2]);
    mp = fmaxf(mp, t0s[ty+2][tx]);   mp = fmaxf(mp, t0s[ty+2][tx+1]); mp = fmaxf(mp, t0s[ty+2][tx+2]);

    size_t pix = (size_t)i*480 + j;
    size_t ob  = (size_t)b*20*NM + pix;
    const float* ml = maps_last + ob;
    bool eve0 = (eve[b] == 0.0f);

    float mask = 1.0f;
    if (b == 0) {
        float dy = (float)i - (float)g_sxy[1] + 0.5f;
        float dx = (float)j - (float)g_sxy[0] + 0.5f;
        mask = (dy*dy + dx*dx <= 900.0f) ? 1.0f : 0.0f;
    }

    if (!inbox) {
        // t=0 everywhere; mp>=0 so dth/dsth can't fire (t1=0)
        #pragma unroll
        for (int c=0;c<20;c++) {
            float m = fmaxf(ml[(size_t)c*NM], 0.0f);
            out_t[ob + (size_t)c*NM] = 0.0f;
            out_p[ob + (size_t)c*NM] = m;
            out_s[ob + (size_t)c*NM] = m;
        }
        return;
    }

    const uint16_t* myo = soff[tid];
    const float*    myw = swt[tid];

    float t1    = gather_smem(pb + 10000,    myo, myw);
    float tst   = gather_smem(pb + 18*10000, myo, myw);   // stair plane
    bool dth  = (t1 - mp) > 0.8f;
    float ts0 = tst * mask;
    float ts1 = (b == 0) ? t1*mask : t1;
    bool dsth = (ts1 - ts0) > 0.8f;

    float ml0 = ml[0], ml1 = ml[(size_t)NM];
    out_t[ob]              = t0;
    out_t[ob + (size_t)NM] = t1;
    out_p[ob]              = (eve0 && dth)  ? 0.0f : fmaxf(ml0, t0);
    out_p[ob + (size_t)NM] = fmaxf(ml1, t1);
    out_s[ob]              = (eve0 && dsth) ? 0.0f : fmaxf(ml0, ts0);
    out_s[ob + (size_t)NM] = fmaxf(ml1, ts1);

    // channels 2,3 always zero in agent_view
    #pragma unroll
    for (int c=2;c<4;c++) {
        float m = fmaxf(ml[(size_t)c*NM], 0.0f);
        out_t[ob + (size_t)c*NM] = 0.0f;
        out_p[ob + (size_t)c*NM] = m;
        out_s[ob + (size_t)c*NM] = m;
    }
    // sem channels 4..19 from planes 2..17
    #pragma unroll 2
    for (int p=2;p<=17;p++) {
        int c = p + 2;
        float acc = gather_smem(pb + (size_t)p*10000, myo, myw);
        float m = fmaxf(ml[(size_t)c*NM], acc);
        out_t[ob + (size_t)c*NM] = acc;
        out_p[ob + (size_t)c*NM] = m;
        out_s[ob + (size_t)c*NM] = m;
    }
}

// ---------------- launch ----------------
extern "C" void kernel_launch(void* const* d_in, const int* in_sizes, int n_in,
                              void* d_out, int out_size) {
    const float* obs        = (const float*)d_in[0];
    const float* pose_obs   = (const float*)d_in[1];
    const float* maps_last  = (const float*)d_in[2];
    const float* poses_last = (const float*)d_in[3];
    const float* eve        = (const float*)d_in[4];
    float* out   = (float*)d_out;
    float* out_p = out + (size_t)N1;
    float* out_s = out + (size_t)2*N1;

    float camf = (float)(320.0 / tan(39.5 * 3.14159265358979323846 / 180.0));

    k_pose   <<<1, 8>>>(pose_obs, poses_last, out + (size_t)3*N1);
    k_splat  <<<(8*240*320 + 255)/256, 256>>>(obs, eve, camf);
    k_projall<<<(NSEM_T + 8*100*100 + 255)/256, 256>>>();
    dim3 grid(30, 30, 8), blk(256);
    k_out    <<<grid, blk>>>(maps_last, eve, out, out_p, out_s);
}